// round 13
// baseline (speedup 1.0000x reference)
#include <cuda_runtime.h>
#include <cstdint>

// out[b,h,w,c] = x[b,h,w,c] + (c < 512 ? spatial_pe[h,w,c]
//                                      : pattern_pe[pattern_indices[b,h,w] % 64][c-512])
// x [64,30,30,1024] f32, pattern_indices [64,30,30] i32,
// spatial_pe [30,30,512] f32, pattern_pe [64,512] f32.  H==W==30.
//
// Record kernel (72.19 us, 6.42 TB/s = 81% DRAM-active) + one single-variable
// probe: st.global.cs (evict-first) on the output stream so dirty writeback
// sectors leave L2 eagerly instead of contending with the x read stream.
//
// 128-thr blocks, 2 pixels per block. Thread t owns the 32-byte channel
// chunk t of both pixels (t<64 -> spatial half, t>=64 -> pattern half;
// warp-uniform). Per thread: 2 front-batched x LDG.256 + 2 PE LDG.256
// (L2-resident) + 2 STG.256.cs.

static constexpr int HW      = 900;    // 30*30
static constexpr int NPIX    = 64 * HW;        // 57600
static constexpr int NBLK    = NPIX / 2;       // 28800
static constexpr int NUM_PAT = 64;
static constexpr int PIX_BYTES  = 1024 * 4;    // 4096 B per pixel
static constexpr int HALF_BYTES = 512 * 4;     // 2048 B per PE row

struct f8 { float v[8]; };

__device__ __forceinline__ f8 ldg256(const void* p) {
    f8 r;
    asm("ld.global.nc.v8.f32 {%0,%1,%2,%3,%4,%5,%6,%7}, [%8];"
        : "=f"(r.v[0]), "=f"(r.v[1]), "=f"(r.v[2]), "=f"(r.v[3]),
          "=f"(r.v[4]), "=f"(r.v[5]), "=f"(r.v[6]), "=f"(r.v[7])
        : "l"(p));
    return r;
}

__device__ __forceinline__ void stg256cs(void* p, const f8& r) {
    asm volatile("st.global.cs.v8.f32 [%0], {%1,%2,%3,%4,%5,%6,%7,%8};"
        :: "l"(p),
           "f"(r.v[0]), "f"(r.v[1]), "f"(r.v[2]), "f"(r.v[3]),
           "f"(r.v[4]), "f"(r.v[5]), "f"(r.v[6]), "f"(r.v[7])
        : "memory");
}

__global__ void __launch_bounds__(128)
pe_add_kernel(const char* __restrict__ xb,
              const int*  __restrict__ pidx,
              const char* __restrict__ spb,   // spatial_pe bytes: 900 rows x 2048 B
              const char* __restrict__ ppb,   // pattern_pe bytes:  64 rows x 2048 B
              char*       __restrict__ outb)
{
    const int t    = threadIdx.x;              // 0..127: 32-B chunk within pixel
    const int pix0 = blockIdx.x * 2;           // even; never straddles an image
    const int b    = pix0 / HW;
    const int hw0  = pix0 - b * HW;

    // pattern indices for both pixels (one 8-B warp-uniform load)
    const int2 pi = __ldg(reinterpret_cast<const int2*>(pidx + pix0));

    const long long base = (long long)pix0 * PIX_BYTES + t * 32;

    // ---- front-batched x loads (2 x LDG.256, DRAM) ----
    f8 x0 = ldg256(xb + base);
    f8 x1 = ldg256(xb + base + PIX_BYTES);

    // ---- PE loads (2 x LDG.256, L2-resident), warp-uniform branch ----
    f8 pe0, pe1;
    if (t < 64) {                              // spatial half (channels < 512)
        const char* s = spb + (long long)hw0 * HALF_BYTES + t * 32;
        pe0 = ldg256(s);
        pe1 = ldg256(s + HALF_BYTES);          // spatial_pe[hw0+1]
    } else {                                   // pattern half
        const int co = (t - 64) * 32;
        pe0 = ldg256(ppb + (long long)(((unsigned)pi.x) % NUM_PAT) * HALF_BYTES + co);
        pe1 = ldg256(ppb + (long long)(((unsigned)pi.y) % NUM_PAT) * HALF_BYTES + co);
    }

#pragma unroll
    for (int i = 0; i < 8; i++) { x0.v[i] += pe0.v[i]; x1.v[i] += pe1.v[i]; }

    stg256cs(outb + base, x0);
    stg256cs(outb + base + PIX_BYTES, x1);
}

extern "C" void kernel_launch(void* const* d_in, const int* in_sizes, int n_in,
                              void* d_out, int out_size)
{
    const char* xb   = (const char*)d_in[0];
    const int*  pidx = (const int*)d_in[1];
    const char* spb  = (const char*)d_in[2];
    const char* ppb  = (const char*)d_in[3];
    char*       outb = (char*)d_out;

    pe_add_kernel<<<NBLK, 128>>>(xb, pidx, spb, ppb, outb);  // 28800 blocks
}

// round 14
// speedup vs baseline: 1.0182x; 1.0182x over previous
#include <cuda_runtime.h>
#include <cstdint>

// out[b,h,w,c] = x[b,h,w,c] + (c < 512 ? spatial_pe[h,w,c]
//                                      : pattern_pe[pattern_indices[b,h,w] % 64][c-512])
// x [64,30,30,1024] f32, pattern_indices [64,30,30] i32,
// spatial_pe [30,30,512] f32, pattern_pe [64,512] f32.  H==W==30.
//
// FINAL — best of 13 measured variants (72.19 us bench, 66.0 us kernel,
// 6.42 TB/s = 81% DRAM-active; reproduced twice bit-identically).
// The kernel sits at the mixed read/write HBM turnaround ceiling: MLP,
// occupancy, cp.async pipelining, persistent launch, cache-policy hints all
// falsified as binding constraints across R3-R13.
//
// 128-thr blocks, 2 pixels per block. Thread t owns the 32-byte channel
// chunk t of both pixels (t<64 -> spatial half, t>=64 -> pattern half;
// warp-uniform split). Per thread: 2 front-batched x LDG.256 (DRAM) +
// 2 PE LDG.256 (L2-resident) + 2 STG.256.

static constexpr int HW      = 900;    // 30*30
static constexpr int NPIX    = 64 * HW;        // 57600
static constexpr int NBLK    = NPIX / 2;       // 28800
static constexpr int NUM_PAT = 64;
static constexpr int PIX_BYTES  = 1024 * 4;    // 4096 B per pixel
static constexpr int HALF_BYTES = 512 * 4;     // 2048 B per PE row

struct f8 { float v[8]; };

__device__ __forceinline__ f8 ldg256(const void* p) {
    f8 r;
    asm("ld.global.nc.v8.f32 {%0,%1,%2,%3,%4,%5,%6,%7}, [%8];"
        : "=f"(r.v[0]), "=f"(r.v[1]), "=f"(r.v[2]), "=f"(r.v[3]),
          "=f"(r.v[4]), "=f"(r.v[5]), "=f"(r.v[6]), "=f"(r.v[7])
        : "l"(p));
    return r;
}

__device__ __forceinline__ void stg256(void* p, const f8& r) {
    asm volatile("st.global.v8.f32 [%0], {%1,%2,%3,%4,%5,%6,%7,%8};"
        :: "l"(p),
           "f"(r.v[0]), "f"(r.v[1]), "f"(r.v[2]), "f"(r.v[3]),
           "f"(r.v[4]), "f"(r.v[5]), "f"(r.v[6]), "f"(r.v[7])
        : "memory");
}

__global__ void __launch_bounds__(128)
pe_add_kernel(const char* __restrict__ xb,
              const int*  __restrict__ pidx,
              const char* __restrict__ spb,   // spatial_pe bytes: 900 rows x 2048 B
              const char* __restrict__ ppb,   // pattern_pe bytes:  64 rows x 2048 B
              char*       __restrict__ outb)
{
    const int t    = threadIdx.x;              // 0..127: 32-B chunk within pixel
    const int pix0 = blockIdx.x * 2;           // even; never straddles an image
    const int b    = pix0 / HW;
    const int hw0  = pix0 - b * HW;

    // pattern indices for both pixels (one 8-B warp-uniform load)
    const int2 pi = __ldg(reinterpret_cast<const int2*>(pidx + pix0));

    const long long base = (long long)pix0 * PIX_BYTES + t * 32;

    // ---- front-batched x loads (2 x LDG.256, DRAM) ----
    f8 x0 = ldg256(xb + base);
    f8 x1 = ldg256(xb + base + PIX_BYTES);

    // ---- PE loads (2 x LDG.256, L2-resident), warp-uniform branch ----
    f8 pe0, pe1;
    if (t < 64) {                              // spatial half (channels < 512)
        const char* s = spb + (long long)hw0 * HALF_BYTES + t * 32;
        pe0 = ldg256(s);
        pe1 = ldg256(s + HALF_BYTES);          // spatial_pe[hw0+1]
    } else {                                   // pattern half
        const int co = (t - 64) * 32;
        pe0 = ldg256(ppb + (long long)(((unsigned)pi.x) % NUM_PAT) * HALF_BYTES + co);
        pe1 = ldg256(ppb + (long long)(((unsigned)pi.y) % NUM_PAT) * HALF_BYTES + co);
    }

#pragma unroll
    for (int i = 0; i < 8; i++) { x0.v[i] += pe0.v[i]; x1.v[i] += pe1.v[i]; }

    stg256(outb + base, x0);
    stg256(outb + base + PIX_BYTES, x1);
}

extern "C" void kernel_launch(void* const* d_in, const int* in_sizes, int n_in,
                              void* d_out, int out_size)
{
    const char* xb   = (const char*)d_in[0];
    const int*  pidx = (const int*)d_in[1];
    const char* spb  = (const char*)d_in[2];
    const char* ppb  = (const char*)d_in[3];
    char*       outb = (char*)d_out;

    pe_add_kernel<<<NBLK, 128>>>(xb, pidx, spb, ppb, outb);  // 28800 blocks
}

// round 15
// speedup vs baseline: 1.0186x; 1.0004x over previous
#include <cuda_runtime.h>
#include <cstdint>

// out[b,h,w,c] = x[b,h,w,c] + (c < 512 ? spatial_pe[h,w,c]
//                                      : pattern_pe[pattern_indices[b,h,w] % 64][c-512])
// x [64,30,30,1024] f32, pattern_indices [64,30,30] i32,
// spatial_pe [30,30,512] f32, pattern_pe [64,512] f32.  H==W==30.
//
// FINAL — best of 14 measured variants (72.19 us bench, 66.0-66.3 us kernel,
// up to 6.42 TB/s = 81% DRAM-active; reproduced bit-identically four times).
// The kernel sits at the mixed 1:1 read/write HBM turnaround ceiling:
// MLP depth, occupancy, cp.async pipelining, persistent launch, cache-policy
// hints, and grid ordering were all falsified as binding constraints (R3-R13).
// DRAM traffic is minimal (x read once, out written once, PE tables
// L2-resident); compute pipes <7% busy.
//
// Structure: 128-thr blocks, 2 pixels per block. Thread t owns the 32-byte
// channel chunk t of both pixels (t<64 -> spatial half, t>=64 -> pattern
// half; warp-uniform split). Per thread: 2 front-batched x LDG.256 (DRAM) +
// 2 PE LDG.256 (L2-resident) + 2 STG.256.

static constexpr int HW      = 900;    // 30*30
static constexpr int NPIX    = 64 * HW;        // 57600
static constexpr int NBLK    = NPIX / 2;       // 28800
static constexpr int NUM_PAT = 64;
static constexpr int PIX_BYTES  = 1024 * 4;    // 4096 B per pixel
static constexpr int HALF_BYTES = 512 * 4;     // 2048 B per PE row

struct f8 { float v[8]; };

__device__ __forceinline__ f8 ldg256(const void* p) {
    f8 r;
    asm("ld.global.nc.v8.f32 {%0,%1,%2,%3,%4,%5,%6,%7}, [%8];"
        : "=f"(r.v[0]), "=f"(r.v[1]), "=f"(r.v[2]), "=f"(r.v[3]),
          "=f"(r.v[4]), "=f"(r.v[5]), "=f"(r.v[6]), "=f"(r.v[7])
        : "l"(p));
    return r;
}

__device__ __forceinline__ void stg256(void* p, const f8& r) {
    asm volatile("st.global.v8.f32 [%0], {%1,%2,%3,%4,%5,%6,%7,%8};"
        :: "l"(p),
           "f"(r.v[0]), "f"(r.v[1]), "f"(r.v[2]), "f"(r.v[3]),
           "f"(r.v[4]), "f"(r.v[5]), "f"(r.v[6]), "f"(r.v[7])
        : "memory");
}

__global__ void __launch_bounds__(128)
pe_add_kernel(const char* __restrict__ xb,
              const int*  __restrict__ pidx,
              const char* __restrict__ spb,   // spatial_pe bytes: 900 rows x 2048 B
              const char* __restrict__ ppb,   // pattern_pe bytes:  64 rows x 2048 B
              char*       __restrict__ outb)
{
    const int t    = threadIdx.x;              // 0..127: 32-B chunk within pixel
    const int pix0 = blockIdx.x * 2;           // even; never straddles an image
    const int b    = pix0 / HW;
    const int hw0  = pix0 - b * HW;

    // pattern indices for both pixels (one 8-B warp-uniform load)
    const int2 pi = __ldg(reinterpret_cast<const int2*>(pidx + pix0));

    const long long base = (long long)pix0 * PIX_BYTES + t * 32;

    // ---- front-batched x loads (2 x LDG.256, DRAM) ----
    f8 x0 = ldg256(xb + base);
    f8 x1 = ldg256(xb + base + PIX_BYTES);

    // ---- PE loads (2 x LDG.256, L2-resident), warp-uniform branch ----
    f8 pe0, pe1;
    if (t < 64) {                              // spatial half (channels < 512)
        const char* s = spb + (long long)hw0 * HALF_BYTES + t * 32;
        pe0 = ldg256(s);
        pe1 = ldg256(s + HALF_BYTES);          // spatial_pe[hw0+1]
    } else {                                   // pattern half
        const int co = (t - 64) * 32;
        pe0 = ldg256(ppb + (long long)(((unsigned)pi.x) % NUM_PAT) * HALF_BYTES + co);
        pe1 = ldg256(ppb + (long long)(((unsigned)pi.y) % NUM_PAT) * HALF_BYTES + co);
    }

#pragma unroll
    for (int i = 0; i < 8; i++) { x0.v[i] += pe0.v[i]; x1.v[i] += pe1.v[i]; }

    stg256(outb + base, x0);
    stg256(outb + base + PIX_BYTES, x1);
}

extern "C" void kernel_launch(void* const* d_in, const int* in_sizes, int n_in,
                              void* d_out, int out_size)
{
    const char* xb   = (const char*)d_in[0];
    const int*  pidx = (const int*)d_in[1];
    const char* spb  = (const char*)d_in[2];
    const char* ppb  = (const char*)d_in[3];
    char*       outb = (char*)d_out;

    pe_add_kernel<<<NBLK, 128>>>(xb, pidx, spb, ppb, outb);  // 28800 blocks
}